// round 2
// baseline (speedup 1.0000x reference)
#include <cuda_runtime.h>
#include <math.h>
#include <stddef.h>

#define B_TOT 4096
#define T_STEPS 200
#define DS 32
#define DA 8
#define HH 128
#define TH 384   // 3*H
#define KIN 40   // Ds+Da

// Scratch (allocation-free rule: __device__ globals)
__device__ float g_h[B_TOT * HH];    // hidden state, fp32
__device__ float g_gh[B_TOT * TH];   // h @ Whh^T + bhh, fp32

__device__ __forceinline__ float sigf(float x) { return 1.0f / (1.0f + expf(-x)); }

// ---------------------------------------------------------------------------
// init: zero hidden state
// ---------------------------------------------------------------------------
__global__ void init_h_kernel() {
    int i = blockIdx.x * blockDim.x + threadIdx.x;
    if (i < B_TOT * HH) g_h[i] = 0.0f;
}

// ---------------------------------------------------------------------------
// Flow kernel: one flow block layer.
//   inp = [h, t]  (129)
//   r = 0.8*sig(inp@Wr+br); z = 0.4*sig(inp@Wz+bz)
//   u = tanh([r*h, t]@Wh + bh); phi = tanh(tw * t)
//   h' = h + phi*z*(u-h)
// 128 CTAs x 32 rows. 256 threads: n = tid&127 (output col), half = tid>>7
// (16 rows each). Weights (3 x 129x128 fp32 = 198KB) staged in smem.
// ---------------------------------------------------------------------------
#define FLOW_SMEM_FLOATS (3*16512 + 4*128 + 32*128 + 32)

__global__ void __launch_bounds__(256, 1)
flow_kernel(const float* __restrict__ Wr, const float* __restrict__ br,
            const float* __restrict__ Wz, const float* __restrict__ bz,
            const float* __restrict__ Wh, const float* __restrict__ bh,
            const float* __restrict__ tw, const float* __restrict__ t_all,
            float* __restrict__ hids, int t_idx)
{
    extern __shared__ float sm[];
    float* sWr = sm;                  // 129*128
    float* sWz = sWr + 16512;
    float* sWh = sWz + 16512;
    float* sbr = sWh + 16512;         // 128
    float* sbz = sbr + 128;
    float* sbh = sbz + 128;
    float* stw = sbh + 128;
    float* sIn = stw + 128;           // 32*128
    float* sT  = sIn + 4096;          // 32

    const int tid  = threadIdx.x;
    const int row0 = blockIdx.x * 32;

    // stage weights (coalesced float4)
    {
        const float4* gr = (const float4*)Wr;
        const float4* gz = (const float4*)Wz;
        const float4* gh = (const float4*)Wh;
        float4* s1 = (float4*)sWr; float4* s2 = (float4*)sWz; float4* s3 = (float4*)sWh;
        for (int i = tid; i < 4128; i += 256) { s1[i] = gr[i]; s2[i] = gz[i]; s3[i] = gh[i]; }
    }
    if (tid < 128) { sbr[tid] = br[tid]; sbz[tid] = bz[tid]; sbh[tid] = bh[tid]; stw[tid] = tw[tid]; }
    {
        const float4* gH = (const float4*)(g_h + (size_t)row0 * HH);
        float4* sI = (float4*)sIn;
        for (int i = tid; i < 1024; i += 256) sI[i] = gH[i];
    }
    if (tid < 32) sT[tid] = t_all[(size_t)(row0 + tid) * T_STEPS + t_idx];
    __syncthreads();

    const int n  = tid & 127;
    const int m0 = (tid >> 7) * 16;

    float hc[16], ar[16], az[16];
#pragma unroll
    for (int m = 0; m < 16; m++) {
        hc[m] = sIn[(m0 + m) * HH + n];
        ar[m] = 0.0f; az[m] = 0.0f;
    }

    // r,z matvecs over k=0..127 (vectorized input reads, weights per-column)
    for (int k = 0; k < 128; k += 4) {
        const float wr0 = sWr[(k+0)*HH + n], wr1 = sWr[(k+1)*HH + n];
        const float wr2 = sWr[(k+2)*HH + n], wr3 = sWr[(k+3)*HH + n];
        const float wz0 = sWz[(k+0)*HH + n], wz1 = sWz[(k+1)*HH + n];
        const float wz2 = sWz[(k+2)*HH + n], wz3 = sWz[(k+3)*HH + n];
#pragma unroll
        for (int m = 0; m < 16; m++) {
            const float4 x = *(const float4*)&sIn[(m0 + m) * HH + k];
            ar[m] = fmaf(x.x, wr0, fmaf(x.y, wr1, fmaf(x.z, wr2, fmaf(x.w, wr3, ar[m]))));
            az[m] = fmaf(x.x, wz0, fmaf(x.y, wz1, fmaf(x.z, wz2, fmaf(x.w, wz3, az[m]))));
        }
    }
    // k = 128 (time feature row)
    {
        const float wrt = sWr[128*HH + n], wzt = sWz[128*HH + n];
#pragma unroll
        for (int m = 0; m < 16; m++) {
            const float tv = sT[m0 + m];
            ar[m] = fmaf(tv, wrt, ar[m]);
            az[m] = fmaf(tv, wzt, az[m]);
        }
    }
    float rr[16], zz[16];
    {
        const float bnr = sbr[n], bnz = sbz[n];
#pragma unroll
        for (int m = 0; m < 16; m++) {
            rr[m] = 0.8f * sigf(ar[m] + bnr);   // BETA = 4/5
            zz[m] = 0.4f * sigf(az[m] + bnz);   // ALPHA = 2/5
        }
    }
    __syncthreads();                  // everyone done reading h tile
#pragma unroll
    for (int m = 0; m < 16; m++) sIn[(m0 + m) * HH + n] = rr[m] * hc[m];
    __syncthreads();                  // r*h tile visible

    float au[16];
#pragma unroll
    for (int m = 0; m < 16; m++) au[m] = 0.0f;
    for (int k = 0; k < 128; k += 4) {
        const float wh0 = sWh[(k+0)*HH + n], wh1 = sWh[(k+1)*HH + n];
        const float wh2 = sWh[(k+2)*HH + n], wh3 = sWh[(k+3)*HH + n];
#pragma unroll
        for (int m = 0; m < 16; m++) {
            const float4 x = *(const float4*)&sIn[(m0 + m) * HH + k];
            au[m] = fmaf(x.x, wh0, fmaf(x.y, wh1, fmaf(x.z, wh2, fmaf(x.w, wh3, au[m]))));
        }
    }
    {
        const float wht = sWh[128*HH + n];
        const float bnh = sbh[n];
        const float twn = stw[n];
#pragma unroll
        for (int m = 0; m < 16; m++) {
            const float tv  = sT[m0 + m];
            const float u   = tanhf(fmaf(tv, wht, au[m]) + bnh);
            const float phi = tanhf(twn * tv);
            const float hn  = hc[m] + phi * zz[m] * (u - hc[m]);
            const int row   = row0 + m0 + m;
            g_h[(size_t)row * HH + n] = hn;
            if (hids) hids[((size_t)row * T_STEPS + t_idx) * HH + n] = hn;
        }
    }
}

// ---------------------------------------------------------------------------
// gh kernel: g_gh = h @ Whh^T + bhh   (Whh: [384,128] fp32, 192KB in smem,
// stored transposed with pad-385 to keep both the transpose-write and the
// per-column compute read conflict-free). 128 CTAs x 32 rows, 384 threads.
// ---------------------------------------------------------------------------
#define GH_SMEM_FLOATS (128*385 + 384 + 32*128)

__global__ void __launch_bounds__(384, 1)
gh_kernel(const float* __restrict__ Whh, const float* __restrict__ bhh)
{
    extern __shared__ float sm[];
    float* sW  = sm;            // [k*385 + j], 128x384 padded
    float* sb  = sW + 128*385;  // 384
    float* sIn = sb + 384;      // 32*128

    const int tid  = threadIdx.x;
    const int row0 = blockIdx.x * 32;

    for (int idx = tid; idx < TH * HH; idx += 384) {
        const int j = idx >> 7;       // 0..383
        const int k = idx & 127;      // 0..127
        sW[k * 385 + j] = Whh[idx];
    }
    sb[tid] = bhh[tid];
    {
        const float4* gH = (const float4*)(g_h + (size_t)row0 * HH);
        float4* sI = (float4*)sIn;
        for (int i = tid; i < 1024; i += 384) sI[i] = gH[i];
    }
    __syncthreads();

    float acc[32];
#pragma unroll
    for (int m = 0; m < 32; m++) acc[m] = 0.0f;

    for (int k = 0; k < 128; k += 4) {
        const float w0 = sW[(k+0)*385 + tid], w1 = sW[(k+1)*385 + tid];
        const float w2 = sW[(k+2)*385 + tid], w3 = sW[(k+3)*385 + tid];
#pragma unroll
        for (int m = 0; m < 32; m++) {
            const float4 x = *(const float4*)&sIn[m * HH + k];
            acc[m] = fmaf(x.x, w0, fmaf(x.y, w1, fmaf(x.z, w2, fmaf(x.w, w3, acc[m]))));
        }
    }
    const float b = sb[tid];
#pragma unroll
    for (int m = 0; m < 32; m++)
        g_gh[(size_t)(row0 + m) * TH + tid] = acc[m] + b;
}

// ---------------------------------------------------------------------------
// GRU + decoder kernel:
//   gi = x@Wih^T + bih ; r,z = sig ; n = tanh(gi_n + r*gh_n)
//   h' = (1-z)n + z*h ; o = h'@decW^T + dec_b
// 128 CTAs x 32 rows, 128 threads (thread n = hidden unit; 3 gates each).
// ---------------------------------------------------------------------------
#define GRU_SMEM_FLOATS (40*385 + 128*33 + 32*384 + 32*40 + 32*128 + 32*128 + 384 + 32)

__global__ void __launch_bounds__(128, 1)
gru_kernel(const float* __restrict__ s_in, const float* __restrict__ a_in,
           const float* __restrict__ Wih,  const float* __restrict__ bih,
           const float* __restrict__ decW, const float* __restrict__ decb,
           float* __restrict__ outs, int t_idx)
{
    extern __shared__ float sm[];
    float* sWih = sm;             // [k*385 + j], 40x384 padded
    float* sDec = sWih + 40*385;  // [k*33 + d], 128x32 padded
    float* sGh  = sDec + 128*33;  // 32*384
    float* sX   = sGh + 32*384;   // 32*40
    float* sHp  = sX + 32*40;     // 32*128  (h after flow)
    float* sHn  = sHp + 32*128;   // 32*128  (h_new)
    float* sBih = sHn + 32*128;   // 384
    float* sDb  = sBih + 384;     // 32

    const int tid  = threadIdx.x;
    const int row0 = blockIdx.x * 32;

    for (int idx = tid; idx < TH * KIN; idx += 128) {
        const int j = idx / KIN;
        const int k = idx - j * KIN;
        sWih[k * 385 + j] = Wih[idx];
    }
    for (int idx = tid; idx < DS * HH; idx += 128) {
        const int d = idx >> 7;
        const int k = idx & 127;
        sDec[k * 33 + d] = decW[idx];
    }
    {
        const float4* gG = (const float4*)(g_gh + (size_t)row0 * TH);
        float4* sG = (float4*)sGh;
        for (int i = tid; i < (32 * TH) / 4; i += 128) sG[i] = gG[i];
        const float4* gH = (const float4*)(g_h + (size_t)row0 * HH);
        float4* sH = (float4*)sHp;
        for (int i = tid; i < 1024; i += 128) sH[i] = gH[i];
    }
    for (int idx = tid; idx < 32 * KIN; idx += 128) {
        const int m = idx / KIN;
        const int c = idx - m * KIN;
        const size_t row = row0 + m;
        sX[idx] = (c < DS) ? s_in[(row * T_STEPS + t_idx) * DS + c]
                           : a_in[(row * T_STEPS + t_idx) * DA + (c - DS)];
    }
    for (int idx = tid; idx < TH; idx += 128) sBih[idx] = bih[idx];
    if (tid < 32) sDb[tid] = decb[tid];
    __syncthreads();

    const int n = tid;
    const float b_r = sBih[n], b_z = sBih[128 + n], b_n = sBih[256 + n];

    // process rows in subtiles of 8 (weights hoisted over rows)
    for (int ms = 0; ms < 4; ms++) {
        float gr[8], gz[8], gn[8];
#pragma unroll
        for (int mm = 0; mm < 8; mm++) { gr[mm] = b_r; gz[mm] = b_z; gn[mm] = b_n; }
        for (int k = 0; k < KIN; k++) {
            const float wr = sWih[k*385 + n];
            const float wz = sWih[k*385 + 128 + n];
            const float wn = sWih[k*385 + 256 + n];
#pragma unroll
            for (int mm = 0; mm < 8; mm++) {
                const float x = sX[(ms*8 + mm) * KIN + k];
                gr[mm] = fmaf(x, wr, gr[mm]);
                gz[mm] = fmaf(x, wz, gz[mm]);
                gn[mm] = fmaf(x, wn, gn[mm]);
            }
        }
#pragma unroll
        for (int mm = 0; mm < 8; mm++) {
            const int m   = ms*8 + mm;
            const float ghr = sGh[m*TH + n];
            const float ghz = sGh[m*TH + 128 + n];
            const float ghn = sGh[m*TH + 256 + n];
            const float h   = sHp[m*HH + n];
            const float r   = sigf(gr[mm] + ghr);
            const float z   = sigf(gz[mm] + ghz);
            const float nn  = tanhf(fmaf(r, ghn, gn[mm]));
            const float hn  = (1.0f - z) * nn + z * h;
            g_h[(size_t)(row0 + m) * HH + n] = hn;
            sHn[m*HH + n] = hn;
        }
    }
    __syncthreads();

    // decoder: threads = 32 cols x 4 row-groups of 8
    const int d  = tid & 31;
    const int mg = tid >> 5;
#pragma unroll
    for (int mm = 0; mm < 8; mm++) {
        const int m = mg * 8 + mm;
        float acc = sDb[d];
        for (int k = 0; k < 128; k += 4) {
            const float4 hv = *(const float4*)&sHn[m * HH + k];
            acc = fmaf(hv.x, sDec[(k+0)*33 + d], acc);
            acc = fmaf(hv.y, sDec[(k+1)*33 + d], acc);
            acc = fmaf(hv.z, sDec[(k+2)*33 + d], acc);
            acc = fmaf(hv.w, sDec[(k+3)*33 + d], acc);
        }
        const size_t row = row0 + m;
        outs[(row * T_STEPS + t_idx) * DS + d] = acc;
    }
}

// ---------------------------------------------------------------------------
// launch
// ---------------------------------------------------------------------------
extern "C" void kernel_launch(void* const* d_in, const int* in_sizes, int n_in,
                              void* d_out, int out_size)
{
    const float* s    = (const float*)d_in[0];
    const float* a    = (const float*)d_in[1];
    const float* t    = (const float*)d_in[2];
    const float* fWr  = (const float*)d_in[3];
    const float* fbr  = (const float*)d_in[4];
    const float* fWz  = (const float*)d_in[5];
    const float* fbz  = (const float*)d_in[6];
    const float* fWh  = (const float*)d_in[7];
    const float* fbh  = (const float*)d_in[8];
    const float* ftw  = (const float*)d_in[9];
    const float* Wih  = (const float*)d_in[10];
    const float* Whh  = (const float*)d_in[11];
    const float* bih  = (const float*)d_in[12];
    const float* bhh  = (const float*)d_in[13];
    const float* decW = (const float*)d_in[14];
    const float* decb = (const float*)d_in[15];

    float* outs = (float*)d_out;
    float* hids = outs + (size_t)B_TOT * T_STEPS * DS;

    const int FLOW_SMEM = FLOW_SMEM_FLOATS * 4;
    const int GH_SMEM   = GH_SMEM_FLOATS * 4;
    const int GRU_SMEM  = GRU_SMEM_FLOATS * 4;

    cudaFuncSetAttribute(flow_kernel, cudaFuncAttributeMaxDynamicSharedMemorySize, FLOW_SMEM);
    cudaFuncSetAttribute(gh_kernel,   cudaFuncAttributeMaxDynamicSharedMemorySize, GH_SMEM);
    cudaFuncSetAttribute(gru_kernel,  cudaFuncAttributeMaxDynamicSharedMemorySize, GRU_SMEM);

    init_h_kernel<<<(B_TOT * HH + 255) / 256, 256>>>();

    const int WSTRIDE = 129 * HH;  // per-layer flow weight stride
    for (int ti = 0; ti < T_STEPS; ti++) {
        flow_kernel<<<128, 256, FLOW_SMEM>>>(fWr, fbr, fWz, fbz, fWh, fbh, ftw,
                                             t, (float*)0, ti);
        flow_kernel<<<128, 256, FLOW_SMEM>>>(fWr + WSTRIDE, fbr + HH,
                                             fWz + WSTRIDE, fbz + HH,
                                             fWh + WSTRIDE, fbh + HH,
                                             ftw + HH, t, hids, ti);
        gh_kernel<<<128, 384, GH_SMEM>>>(Whh, bhh);
        gru_kernel<<<128, 128, GRU_SMEM>>>(s, a, Wih, bih, decW, decb, outs, ti);
    }
}